// round 10
// baseline (speedup 1.0000x reference)
#include <cuda_runtime.h>
#include <math.h>
#include <stdint.h>

// Problem constants (fixed by the reference)
#define DM    1024
#define HH    16
#define DKH   64
#define BATCH 4
#define SEQ   2048
#define MTOT  (BATCH * SEQ)   // 8192

// ---------------------------------------------------------------------------
// Scratch (no allocations allowed -> __device__ globals)
// ---------------------------------------------------------------------------
__device__ __align__(128) float g_Q[(size_t)MTOT * DM];
__device__ __align__(128) float g_K[(size_t)MTOT * DM];
__device__ __align__(128) float g_V[(size_t)MTOT * DM];
__device__ __align__(128) float g_ctx[(size_t)MTOT * DM];
// tf32-preconverted copies of inputs (preserves R5 rounding semantics)
__device__ __align__(128) float c_q[(size_t)MTOT * DM];
__device__ __align__(128) float c_k[(size_t)MTOT * DM];
__device__ __align__(128) float c_v[(size_t)MTOT * DM];
__device__ __align__(128) float c_Wq[(size_t)DM * DM];
__device__ __align__(128) float c_Wk[(size_t)DM * DM];
__device__ __align__(128) float c_Wv[(size_t)DM * DM];
__device__ __align__(128) float c_Wo[(size_t)DM * DM];

// ---------------------------------------------------------------------------
// Helpers
// ---------------------------------------------------------------------------
__device__ __forceinline__ float f2tf32(float x) {
    uint32_t r;
    asm("cvt.rna.tf32.f32 %0, %1;" : "=r"(r) : "f"(x));
    return __uint_as_float(r);
}

__device__ __forceinline__ void mma_tf32(float (&d)[4],
                                         const uint32_t (&a)[4],
                                         const uint32_t (&b)[2]) {
    asm volatile(
        "mma.sync.aligned.m16n8k8.row.col.f32.tf32.tf32.f32 "
        "{%0,%1,%2,%3}, {%4,%5,%6,%7}, {%8,%9}, {%0,%1,%2,%3};"
        : "+f"(d[0]), "+f"(d[1]), "+f"(d[2]), "+f"(d[3])
        : "r"(a[0]), "r"(a[1]), "r"(a[2]), "r"(a[3]),
          "r"(b[0]), "r"(b[1]));
}

__device__ __forceinline__ void cp16(uint32_t dst_smem, const void* src) {
    asm volatile("cp.async.cg.shared.global [%0], [%1], 16;"
                 :: "r"(dst_smem), "l"(src));
}
__device__ __forceinline__ void cp_commit() {
    asm volatile("cp.async.commit_group;");
}
template <int N>
__device__ __forceinline__ void cp_wait() {
    asm volatile("cp.async.wait_group %0;" :: "n"(N));
}

// ---------------------------------------------------------------------------
// Fused elementwise tf32 pre-convert: one launch converts all 7 tensors.
// ---------------------------------------------------------------------------
struct ConvArgs {
    const float4* src[7];
    float4*       dst[7];
    int           n4[7];
};

__global__ __launch_bounds__(256)
void conv_all_kernel(ConvArgs a)
{
    const int seg = blockIdx.y;
    const float4* __restrict__ in = a.src[seg];
    float4* __restrict__ out = a.dst[seg];
    const int n4 = a.n4[seg];
    int base = blockIdx.x * 1024 + threadIdx.x;
    if (base >= n4) return;
#pragma unroll
    for (int j = 0; j < 4; j++) {
        int i = base + j * 256;
        if (i < n4) {
            float4 v = in[i];
            out[i] = make_float4(f2tf32(v.x), f2tf32(v.y), f2tf32(v.z), f2tf32(v.w));
        }
    }
}

// ---------------------------------------------------------------------------
// cp.async pipelined TF32 GEMM NT body: C[M,N] = A[M,K] * B[N,K]^T
// Inputs already tf32-rounded. CTA tile 128x128, BK=32, 3 stages (96KB),
// one __syncthreads per iteration. Designed for 2 CTAs/SM (regs <= 128 via
// __launch_bounds__(256,2)): 16 warps/SM to fill barrier/scoreboard gaps.
// mode: 0 = plain f32 store, 1 = tf32 store, 2 = tf32(0.125*x) (Q proj).
// ---------------------------------------------------------------------------
#define TBK 32
#define NST 3
#define NKB2 (DM / TBK)                   // 32
#define ARR_BYTES (128 * TBK * 4)         // 16KB per array per stage
#define STG_BYTES (2 * ARR_BYTES)         // 32KB
#define SMEM_G2 (NST * STG_BYTES)         // 96KB

__device__ __forceinline__
void gemm_body(const float* __restrict__ A,
               const float* __restrict__ B,
               float* __restrict__ C, int mode)
{
    extern __shared__ __align__(128) float smf[];
    const uint32_t smem_base = (uint32_t)__cvta_generic_to_shared(smf);

    const int tid = threadIdx.x;
    const int bn = blockIdx.x * 128;
    const int bm = blockIdx.y * 128;

    const int lane = tid & 31;
    const int wid  = tid >> 5;
    const int wm   = wid >> 2;          // 0..1
    const int wn   = wid & 3;           // 0..3
    const int g    = lane >> 2;         // 0..7
    const int tg   = lane & 3;          // 0..3

    float acc[4][4][4];
#pragma unroll
    for (int i = 0; i < 4; i++)
#pragma unroll
        for (int j = 0; j < 4; j++)
#pragma unroll
            for (int c = 0; c < 4; c++) acc[i][j][c] = 0.f;

    // ---- fill one stage: A/B, 128 rows x 8 units(16B) each, swizzled ----
    auto fill = [&](int slot, int kb) {
        const uint32_t ab = smem_base + slot * STG_BYTES;
        const uint32_t bb = ab + ARR_BYTES;
        const float* Ak = A + (size_t)bm * DM + kb * TBK;
        const float* Bk = B + (size_t)bn * DM + kb * TBK;
#pragma unroll
        for (int i = 0; i < 4; i++) {
            int idx = tid + i * 256;        // 0..1023
            int row = idx >> 3;             // 0..127
            int u   = idx & 7;              // 16B unit within 32-float row
            uint32_t off = row * 128 + ((u ^ (row & 7)) << 4);
            cp16(ab + off, Ak + (size_t)row * DM + u * 4);
            cp16(bb + off, Bk + (size_t)row * DM + u * 4);
        }
        cp_commit();
    };

    // swizzled float index for element (row, c) of a 128x32 block, c in [0,32)
    auto sidx = [&](int row, int c) -> int {
        return row * 32 + ((((c) >> 2) ^ (row & 7)) << 2) + (c & 3);
    };

    fill(0, 0);
    fill(1, 1);

    for (int s = 0; s < NKB2; s++) {
        const int slot = s % NST;
        if (s < NKB2 - 1) cp_wait<1>();
        else              cp_wait<0>();
        __syncthreads();

        // refill the slot read at iteration s-1 (fenced by the barrier above)
        if (s + 2 < NKB2) fill((s + 2) % NST, s + 2);

        const float* as = smf + (size_t)slot * (STG_BYTES / 4);
        const float* bs = as + ARR_BYTES / 4;

#pragma unroll
        for (int ks = 0; ks < 4; ks++) {
            uint32_t af[4][4];
            uint32_t bf[4][2];
            const int c0 = ks * 8 + tg;
#pragma unroll
            for (int mf = 0; mf < 4; mf++) {
                const int r0 = wm * 64 + mf * 16 + g;
                af[mf][0] = __float_as_uint(as[sidx(r0,     c0)]);
                af[mf][1] = __float_as_uint(as[sidx(r0 + 8, c0)]);
                af[mf][2] = __float_as_uint(as[sidx(r0,     c0 + 4)]);
                af[mf][3] = __float_as_uint(as[sidx(r0 + 8, c0 + 4)]);
            }
#pragma unroll
            for (int nf = 0; nf < 4; nf++) {
                const int r0 = wn * 32 + nf * 8 + g;
                bf[nf][0] = __float_as_uint(bs[sidx(r0, c0)]);
                bf[nf][1] = __float_as_uint(bs[sidx(r0, c0 + 4)]);
            }
#pragma unroll
            for (int mf = 0; mf < 4; mf++)
#pragma unroll
                for (int nf = 0; nf < 4; nf++)
                    mma_tf32(acc[mf][nf], af[mf], bf[nf]);
        }
    }

    const bool do_round = (mode != 0);
    const float sc = (mode == 2) ? 0.125f : 1.0f;

#pragma unroll
    for (int mf = 0; mf < 4; mf++) {
#pragma unroll
        for (int nf = 0; nf < 4; nf++) {
            float x0 = acc[mf][nf][0] * sc, x1 = acc[mf][nf][1] * sc;
            float x2 = acc[mf][nf][2] * sc, x3 = acc[mf][nf][3] * sc;
            if (do_round) {
                x0 = f2tf32(x0); x1 = f2tf32(x1);
                x2 = f2tf32(x2); x3 = f2tf32(x3);
            }
            float* cp = C + (size_t)(bm + wm * 64 + mf * 16 + g) * DM
                          + bn + wn * 32 + nf * 8 + tg * 2;
            *(float2*)cp = make_float2(x0, x1);
            *(float2*)(cp + 8 * DM) = make_float2(x2, x3);
        }
    }
}

struct QKVArgs {
    const float* A[3];
    const float* B[3];
    float*       C[3];
};

__global__ __launch_bounds__(256, 2)
void gemm_qkv_kernel(QKVArgs a)
{
    const int z = blockIdx.z;
    gemm_body(a.A[z], a.B[z], a.C[z], z == 0 ? 2 : 1);
}

__global__ __launch_bounds__(256, 2)
void gemm_o_kernel(const float* __restrict__ A,
                   const float* __restrict__ B,
                   float* __restrict__ C)
{
    gemm_body(A, B, C, 0);
}

// ---------------------------------------------------------------------------
// Tensor-core flash attention v4 (R8/R9, verified): per-lane l partials,
// reduced across the quad only in the epilogue.
// ---------------------------------------------------------------------------
#define KP 68
#define VP 72
#define QTILE 128
#define NKV   (SEQ / 64)   // 32 kv tiles

__global__ __launch_bounds__(128)
void attn_mma4_kernel(const float* __restrict__ Q,
                      const float* __restrict__ K,
                      const float* __restrict__ V,
                      float* __restrict__ ctx)
{
    const int bh = blockIdx.x;
    const int b  = bh / HH;
    const int h  = bh % HH;
    const int q0 = blockIdx.y * QTILE;

    extern __shared__ float sm[];
    float* Ks = sm;                         // [2][64*KP]
    float* Vs = Ks + 2 * 64 * KP;           // [2][64*VP]

    const int tid  = threadIdx.x;
    const int lane = tid & 31;
    const int warp = tid >> 5;
    const int wq   = warp * 32;
    const int g    = lane >> 2;
    const int tg   = lane & 3;
    const int idx_lo = (lane & ~3) | (tg >> 1);
    const int idx_hi = idx_lo + 2;
    const bool odd = (tg & 1);

    const float* Kbase = K + (size_t)b * SEQ * DM + h * DKH;
    const float* Vbase = V + (size_t)b * SEQ * DM + h * DKH;

    const uint32_t ks_smem = (uint32_t)__cvta_generic_to_shared(Ks);
    const uint32_t vs_smem = (uint32_t)__cvta_generic_to_shared(Vs);

    auto prefetch = [&](int t, int buf) {
#pragma unroll
        for (int i = 0; i < 8; i++) {
            int idx = tid + i * 128;
            int row = idx >> 4;
            int c4  = (idx & 15) * 4;
            const float* ks_src = Kbase + (size_t)(t * 64 + row) * DM + c4;
            const float* vs_src = Vbase + (size_t)(t * 64 + row) * DM + c4;
            cp16(ks_smem + (buf * 64 * KP + row * KP + c4) * 4, ks_src);
            cp16(vs_smem + (buf * 64 * VP + row * VP + c4) * 4, vs_src);
        }
        cp_commit();
    };

    uint32_t qa[2][8][4];
    {
        const float* Qb = Q + ((size_t)b * SEQ + q0 + wq) * DM + h * DKH;
#pragma unroll
        for (int mf = 0; mf < 2; mf++)
#pragma unroll
            for (int ks = 0; ks < 8; ks++) {
                const float* r0 = Qb + (size_t)(mf * 16 + g) * DM + ks * 8 + tg;
                const float* r1 = r0 + (size_t)8 * DM;
                qa[mf][ks][0] = __float_as_uint(r0[0]);
                qa[mf][ks][1] = __float_as_uint(r1[0]);
                qa[mf][ks][2] = __float_as_uint(r0[4]);
                qa[mf][ks][3] = __float_as_uint(r1[4]);
            }
    }

    prefetch(0, 0);

    float m_r[2][2], l_r[2][2];     // l_r = per-lane partial sums
    float Oacc[2][8][4];
#pragma unroll
    for (int mf = 0; mf < 2; mf++) {
        m_r[mf][0] = -INFINITY; m_r[mf][1] = -INFINITY;
        l_r[mf][0] = 0.f;       l_r[mf][1] = 0.f;
#pragma unroll
        for (int nf = 0; nf < 8; nf++)
#pragma unroll
            for (int c = 0; c < 4; c++) Oacc[mf][nf][c] = 0.f;
    }

    int buf = 0;
    for (int t = 0; t < NKV; t++) {
        if (t + 1 < NKV) prefetch(t + 1, buf ^ 1);
        else             cp_commit();
        cp_wait<1>();
        __syncthreads();

        const float* kt = Ks + buf * 64 * KP;
        const float* vt = Vs + buf * 64 * VP;

#pragma unroll
        for (int kc = 0; kc < 2; kc++) {
            float sacc[2][4][4];
#pragma unroll
            for (int mf = 0; mf < 2; mf++)
#pragma unroll
                for (int nf = 0; nf < 4; nf++)
#pragma unroll
                    for (int c = 0; c < 4; c++) sacc[mf][nf][c] = 0.f;

#pragma unroll
            for (int ks = 0; ks < 8; ks++) {
#pragma unroll
                for (int nf = 0; nf < 4; nf++) {
                    const float* p = &kt[(kc * 32 + nf * 8 + g) * KP + ks * 8 + tg];
                    uint32_t bf[2] = {__float_as_uint(p[0]), __float_as_uint(p[4])};
                    mma_tf32(sacc[0][nf], qa[0][ks], bf);
                    mma_tf32(sacc[1][nf], qa[1][ks], bf);
                }
            }

#pragma unroll
            for (int mf = 0; mf < 2; mf++) {
                float mx0 = -INFINITY, mx1 = -INFINITY;
#pragma unroll
                for (int nf = 0; nf < 4; nf++) {
                    mx0 = fmaxf(mx0, fmaxf(sacc[mf][nf][0], sacc[mf][nf][1]));
                    mx1 = fmaxf(mx1, fmaxf(sacc[mf][nf][2], sacc[mf][nf][3]));
                }
                mx0 = fmaxf(mx0, __shfl_xor_sync(0xffffffffu, mx0, 1));
                mx0 = fmaxf(mx0, __shfl_xor_sync(0xffffffffu, mx0, 2));
                mx1 = fmaxf(mx1, __shfl_xor_sync(0xffffffffu, mx1, 1));
                mx1 = fmaxf(mx1, __shfl_xor_sync(0xffffffffu, mx1, 2));

                const float mn0 = fmaxf(m_r[mf][0], mx0);
                const float mn1 = fmaxf(m_r[mf][1], mx1);
                const float al0 = __expf(m_r[mf][0] - mn0);
                const float al1 = __expf(m_r[mf][1] - mn1);

                float s0 = 0.f, s1 = 0.f;
#pragma unroll
                for (int nf = 0; nf < 4; nf++) {
                    float p0 = __expf(sacc[mf][nf][0] - mn0);
                    float p1 = __expf(sacc[mf][nf][1] - mn0);
                    float p2 = __expf(sacc[mf][nf][2] - mn1);
                    float p3 = __expf(sacc[mf][nf][3] - mn1);
                    sacc[mf][nf][0] = p0; sacc[mf][nf][1] = p1;
                    sacc[mf][nf][2] = p2; sacc[mf][nf][3] = p3;
                    s0 += p0 + p1;
                    s1 += p2 + p3;
                }
                // per-lane partials: NO shfl reduction here
                m_r[mf][0] = mn0; m_r[mf][1] = mn1;
                l_r[mf][0] = l_r[mf][0] * al0 + s0;
                l_r[mf][1] = l_r[mf][1] * al1 + s1;

#pragma unroll
                for (int nf = 0; nf < 8; nf++) {
                    Oacc[mf][nf][0] *= al0; Oacc[mf][nf][1] *= al0;
                    Oacc[mf][nf][2] *= al1; Oacc[mf][nf][3] *= al1;
                }
            }

            uint32_t af[2][4][4];
#pragma unroll
            for (int mf = 0; mf < 2; mf++)
#pragma unroll
                for (int nf = 0; nf < 4; nf++) {
                    float v0l = __shfl_sync(0xffffffffu, sacc[mf][nf][0], idx_lo);
                    float v1l = __shfl_sync(0xffffffffu, sacc[mf][nf][1], idx_lo);
                    float v2l = __shfl_sync(0xffffffffu, sacc[mf][nf][2], idx_lo);
                    float v3l = __shfl_sync(0xffffffffu, sacc[mf][nf][3], idx_lo);
                    float v0h = __shfl_sync(0xffffffffu, sacc[mf][nf][0], idx_hi);
                    float v1h = __shfl_sync(0xffffffffu, sacc[mf][nf][1], idx_hi);
                    float v2h = __shfl_sync(0xffffffffu, sacc[mf][nf][2], idx_hi);
                    float v3h = __shfl_sync(0xffffffffu, sacc[mf][nf][3], idx_hi);
                    af[mf][nf][0] = __float_as_uint(f2tf32(odd ? v1l : v0l));
                    af[mf][nf][1] = __float_as_uint(f2tf32(odd ? v3l : v2l));
                    af[mf][nf][2] = __float_as_uint(f2tf32(odd ? v1h : v0h));
                    af[mf][nf][3] = __float_as_uint(f2tf32(odd ? v3h : v2h));
                }

#pragma unroll
            for (int ksl = 0; ksl < 4; ksl++) {
#pragma unroll
                for (int nf = 0; nf < 8; nf++) {
                    uint32_t bf[2] = {
                        __float_as_uint(vt[(kc * 32 + ksl * 8 + tg) * VP + nf * 8 + g]),
                        __float_as_uint(vt[(kc * 32 + ksl * 8 + tg + 4) * VP + nf * 8 + g])
                    };
                    mma_tf32(Oacc[0][nf], af[0][ksl], bf);
                    mma_tf32(Oacc[1][nf], af[1][ksl], bf);
                }
            }
        }

        __syncthreads();
        buf ^= 1;
    }

    // epilogue: reduce l across the quad, then tf32-rounded ctx store
#pragma unroll
    for (int mf = 0; mf < 2; mf++) {
        float l0 = l_r[mf][0], l1 = l_r[mf][1];
        l0 += __shfl_xor_sync(0xffffffffu, l0, 1);
        l0 += __shfl_xor_sync(0xffffffffu, l0, 2);
        l1 += __shfl_xor_sync(0xffffffffu, l1, 1);
        l1 += __shfl_xor_sync(0xffffffffu, l1, 2);
        const float inv0 = 1.f / l0;
        const float inv1 = 1.f / l1;
        float* out = ctx + ((size_t)b * SEQ + q0 + wq + mf * 16) * DM + h * DKH;
#pragma unroll
        for (int nf = 0; nf < 8; nf++) {
            *(float2*)&out[(size_t)g * DM + nf * 8 + tg * 2] =
                make_float2(f2tf32(Oacc[mf][nf][0] * inv0), f2tf32(Oacc[mf][nf][1] * inv0));
            *(float2*)&out[(size_t)(g + 8) * DM + nf * 8 + tg * 2] =
                make_float2(f2tf32(Oacc[mf][nf][2] * inv1), f2tf32(Oacc[mf][nf][3] * inv1));
        }
    }
}

// ---------------------------------------------------------------------------
// Launch
// ---------------------------------------------------------------------------
extern "C" void kernel_launch(void* const* d_in, const int* in_sizes, int n_in,
                              void* d_out, int out_size)
{
    (void)in_sizes; (void)n_in; (void)out_size;
    const float* q  = (const float*)d_in[0];
    const float* k  = (const float*)d_in[1];
    const float* v  = (const float*)d_in[2];
    const float* Wq = (const float*)d_in[3];
    const float* Wk = (const float*)d_in[4];
    const float* Wv = (const float*)d_in[5];
    const float* Wo = (const float*)d_in[6];
    float* out = (float*)d_out;

    float *gQ, *gK, *gV, *gC;
    float *cq, *ck, *cv, *cWq, *cWk, *cWv, *cWo;
    cudaGetSymbolAddress((void**)&gQ, g_Q);
    cudaGetSymbolAddress((void**)&gK, g_K);
    cudaGetSymbolAddress((void**)&gV, g_V);
    cudaGetSymbolAddress((void**)&gC, g_ctx);
    cudaGetSymbolAddress((void**)&cq, c_q);
    cudaGetSymbolAddress((void**)&ck, c_k);
    cudaGetSymbolAddress((void**)&cv, c_v);
    cudaGetSymbolAddress((void**)&cWq, c_Wq);
    cudaGetSymbolAddress((void**)&cWk, c_Wk);
    cudaGetSymbolAddress((void**)&cWv, c_Wv);
    cudaGetSymbolAddress((void**)&cWo, c_Wo);

    const int attn_smem = (2 * 64 * KP + 2 * 64 * VP) * (int)sizeof(float); // 71680
    static bool attr_set = false;
    if (!attr_set) {
        cudaFuncSetAttribute(attn_mma4_kernel,
                             cudaFuncAttributeMaxDynamicSharedMemorySize, attn_smem);
        cudaFuncSetAttribute(gemm_qkv_kernel,
                             cudaFuncAttributeMaxDynamicSharedMemorySize, SMEM_G2);
        cudaFuncSetAttribute(gemm_o_kernel,
                             cudaFuncAttributeMaxDynamicSharedMemorySize, SMEM_G2);
        attr_set = true;
    }

    // ---- fused tf32 pre-convert: one launch for all 7 tensors ----
    const int n4_x = MTOT * DM / 4;   // 2M float4
    const int n4_w = DM * DM / 4;     // 256K float4
    ConvArgs ca;
    ca.src[0] = (const float4*)q;  ca.dst[0] = (float4*)cq;  ca.n4[0] = n4_x;
    ca.src[1] = (const float4*)k;  ca.dst[1] = (float4*)ck;  ca.n4[1] = n4_x;
    ca.src[2] = (const float4*)v;  ca.dst[2] = (float4*)cv;  ca.n4[2] = n4_x;
    ca.src[3] = (const float4*)Wq; ca.dst[3] = (float4*)cWq; ca.n4[3] = n4_w;
    ca.src[4] = (const float4*)Wk; ca.dst[4] = (float4*)cWk; ca.n4[4] = n4_w;
    ca.src[5] = (const float4*)Wv; ca.dst[5] = (float4*)cWv; ca.n4[5] = n4_w;
    ca.src[6] = (const float4*)Wo; ca.dst[6] = (float4*)cWo; ca.n4[6] = n4_w;
    dim3 cgrid((n4_x + 1023) / 1024, 7);
    conv_all_kernel<<<cgrid, 256>>>(ca);

    // ---- fused Q/K/V projections: one launch, grid.z selects tensor ----
    QKVArgs qa;
    qa.A[0] = cq; qa.B[0] = cWq; qa.C[0] = gQ;   // mode 2 (scale+tf32)
    qa.A[1] = ck; qa.B[1] = cWk; qa.C[1] = gK;   // mode 1
    qa.A[2] = cv; qa.B[2] = cWv; qa.C[2] = gV;   // mode 1
    dim3 qgrid(DM / 128, MTOT / 128, 3);   // (8, 64, 3) = 1536 blocks
    gemm_qkv_kernel<<<qgrid, 256, SMEM_G2>>>(qa);

    dim3 agrid(BATCH * HH, SEQ / QTILE);   // (64, 16)
    attn_mma4_kernel<<<agrid, 128, attn_smem>>>(gQ, gK, gV, gC);

    dim3 ogrid(DM / 128, MTOT / 128);      // (8, 64)
    gemm_o_kernel<<<ogrid, 256, SMEM_G2>>>(gC, cWo, out);
}

// round 11
// speedup vs baseline: 1.7307x; 1.7307x over previous
#include <cuda_runtime.h>
#include <cuda_fp16.h>
#include <math.h>
#include <stdint.h>

// Problem constants (fixed by the reference)
#define DM    1024
#define HH    16
#define DKH   64
#define BATCH 4
#define SEQ   2048
#define MTOT  (BATCH * SEQ)   // 8192

// ---------------------------------------------------------------------------
// Scratch (no allocations allowed -> __device__ globals)
// ---------------------------------------------------------------------------
// fp16 copies of inputs
__device__ __align__(128) __half h_q[(size_t)MTOT * DM];
__device__ __align__(128) __half h_k[(size_t)MTOT * DM];
__device__ __align__(128) __half h_v[(size_t)MTOT * DM];
__device__ __align__(128) __half h_Wq[(size_t)DM * DM];
__device__ __align__(128) __half h_Wk[(size_t)DM * DM];
__device__ __align__(128) __half h_Wv[(size_t)DM * DM];
__device__ __align__(128) __half h_Wo[(size_t)DM * DM];
// projected tensors (fp16). g_Vt is head-transposed: [b][h][d][s]
__device__ __align__(128) __half g_Qh[(size_t)MTOT * DM];
__device__ __align__(128) __half g_Kh[(size_t)MTOT * DM];
__device__ __align__(128) __half g_Vt[(size_t)MTOT * DM];
__device__ __align__(128) __half g_ctxh[(size_t)MTOT * DM];

// ---------------------------------------------------------------------------
// Helpers
// ---------------------------------------------------------------------------
__device__ __forceinline__ uint32_t packh2(float lo, float hi) {
    __half2 h = __floats2half2_rn(lo, hi);
    return *reinterpret_cast<uint32_t*>(&h);
}

__device__ __forceinline__ void mma_f16(float (&d)[4],
                                        const uint32_t (&a)[4],
                                        const uint32_t (&b)[2]) {
    asm volatile(
        "mma.sync.aligned.m16n8k16.row.col.f32.f16.f16.f32 "
        "{%0,%1,%2,%3}, {%4,%5,%6,%7}, {%8,%9}, {%0,%1,%2,%3};"
        : "+f"(d[0]), "+f"(d[1]), "+f"(d[2]), "+f"(d[3])
        : "r"(a[0]), "r"(a[1]), "r"(a[2]), "r"(a[3]),
          "r"(b[0]), "r"(b[1]));
}

__device__ __forceinline__ void cp16(uint32_t dst_smem, const void* src) {
    asm volatile("cp.async.cg.shared.global [%0], [%1], 16;"
                 :: "r"(dst_smem), "l"(src));
}
__device__ __forceinline__ void cp_commit() {
    asm volatile("cp.async.commit_group;");
}
template <int N>
__device__ __forceinline__ void cp_wait() {
    asm volatile("cp.async.wait_group %0;" :: "n"(N));
}

// swizzled half-index for element (row, k) of a tile with 64-half (128B) rows
__device__ __forceinline__ int hx(int row, int k) {
    return row * 64 + (((k >> 3) ^ (row & 7)) << 3) + (k & 7);
}

// ---------------------------------------------------------------------------
// Fused f32 -> f16 pre-convert: one launch, grid.y selects tensor.
// Each thread-iter: 8 floats in, 8 halfs (16B) out.
// ---------------------------------------------------------------------------
struct ConvArgs {
    const float4* src[7];
    uint4*        dst[7];
    int           n8[7];
};

__global__ __launch_bounds__(256)
void conv_all_kernel(ConvArgs a)
{
    const int seg = blockIdx.y;
    const float4* __restrict__ in = a.src[seg];
    uint4* __restrict__ out = a.dst[seg];
    const int n8 = a.n8[seg];
    int base = blockIdx.x * 1024 + threadIdx.x;
    if (base >= n8) return;
#pragma unroll
    for (int j = 0; j < 4; j++) {
        int i = base + j * 256;
        if (i < n8) {
            float4 v0 = in[2 * i];
            float4 v1 = in[2 * i + 1];
            out[i] = make_uint4(packh2(v0.x, v0.y), packh2(v0.z, v0.w),
                                packh2(v1.x, v1.y), packh2(v1.z, v1.w));
        }
    }
}

// ---------------------------------------------------------------------------
// fp16 cp.async pipelined GEMM NT: C[M,N] = A[M,K] * B[N,K]^T
// CTA tile 128x128, BK=64 halfs (128B rows), 3 stages (96KB), one sync/iter.
// 256 threads = 8 warps (2m x 4n), warp tile 64x32, m16n8k16 fragments.
// mode: 0 = f32 natural store (O), 1 = f16 natural (K),
//       2 = f16 natural * 0.125 (Q), 3 = f16 head-transposed [b,h,d,s] (V).
// ---------------------------------------------------------------------------
#define HBK 64
#define HNST 3
#define HNKB (DM / HBK)                   // 16
#define H_ARR (128 * HBK * 2)             // 16KB per array per stage
#define H_STG (2 * H_ARR)                 // 32KB
#define H_SMEM (HNST * H_STG)             // 96KB

__device__ __forceinline__
void gemm_h_body(const __half* __restrict__ A,
                 const __half* __restrict__ B,
                 void* __restrict__ Cout, int mode)
{
    extern __shared__ __align__(128) __half smh[];
    const uint32_t smem_base = (uint32_t)__cvta_generic_to_shared(smh);

    const int tid = threadIdx.x;
    const int bn = blockIdx.x * 128;
    const int bm = blockIdx.y * 128;

    const int lane = tid & 31;
    const int wid  = tid >> 5;
    const int wm   = wid >> 2;          // 0..1
    const int wn   = wid & 3;           // 0..3
    const int g    = lane >> 2;         // 0..7
    const int tg   = lane & 3;          // 0..3

    float acc[4][4][4];
#pragma unroll
    for (int i = 0; i < 4; i++)
#pragma unroll
        for (int j = 0; j < 4; j++)
#pragma unroll
            for (int c = 0; c < 4; c++) acc[i][j][c] = 0.f;

    // fill one stage: A/B, 128 rows x 8 16B-units each, XOR swizzled
    auto fill = [&](int slot, int kb) {
        const uint32_t ab = smem_base + slot * H_STG;
        const uint32_t bb = ab + H_ARR;
        const __half* Ak = A + (size_t)bm * DM + kb * HBK;
        const __half* Bk = B + (size_t)bn * DM + kb * HBK;
#pragma unroll
        for (int i = 0; i < 4; i++) {
            int idx = tid + i * 256;        // 0..1023
            int row = idx >> 3;             // 0..127
            int u   = idx & 7;              // 16B unit in 128B row
            uint32_t off = row * 128 + ((u ^ (row & 7)) << 4);
            cp16(ab + off, Ak + (size_t)row * DM + u * 8);
            cp16(bb + off, Bk + (size_t)row * DM + u * 8);
        }
        cp_commit();
    };

    fill(0, 0);
    fill(1, 1);

    for (int s = 0; s < HNKB; s++) {
        const int slot = s % HNST;
        if (s < HNKB - 1) cp_wait<1>();
        else              cp_wait<0>();
        __syncthreads();

        if (s + 2 < HNKB) fill((s + 2) % HNST, s + 2);

        const __half* as = smh + (size_t)slot * (H_STG / 2);
        const __half* bs = as + H_ARR / 2;

#pragma unroll
        for (int j = 0; j < 4; j++) {       // k16 steps within BK=64
            uint32_t af[4][4];
            uint32_t bf[4][2];
            const int c0 = j * 16 + 2 * tg;
#pragma unroll
            for (int mf = 0; mf < 4; mf++) {
                const int r0 = wm * 64 + mf * 16 + g;
                af[mf][0] = *(const uint32_t*)(as + hx(r0,     c0));
                af[mf][1] = *(const uint32_t*)(as + hx(r0 + 8, c0));
                af[mf][2] = *(const uint32_t*)(as + hx(r0,     c0 + 8));
                af[mf][3] = *(const uint32_t*)(as + hx(r0 + 8, c0 + 8));
            }
#pragma unroll
            for (int nf = 0; nf < 4; nf++) {
                const int rn = wn * 32 + nf * 8 + g;
                bf[nf][0] = *(const uint32_t*)(bs + hx(rn, c0));
                bf[nf][1] = *(const uint32_t*)(bs + hx(rn, c0 + 8));
            }
#pragma unroll
            for (int mf = 0; mf < 4; mf++)
#pragma unroll
                for (int nf = 0; nf < 4; nf++)
                    mma_f16(acc[mf][nf], af[mf], bf[nf]);
        }
    }

    // ---- epilogue ----
#pragma unroll
    for (int mf = 0; mf < 4; mf++) {
#pragma unroll
        for (int nf = 0; nf < 4; nf++) {
            const int m0 = bm + wm * 64 + mf * 16 + g;
            const int n0 = bn + wn * 32 + nf * 8 + tg * 2;
            float c0v = acc[mf][nf][0], c1v = acc[mf][nf][1];
            float c2v = acc[mf][nf][2], c3v = acc[mf][nf][3];
            if (mode == 0) {
                float* C = (float*)Cout;
                *(float2*)&C[(size_t)m0 * DM + n0] = make_float2(c0v, c1v);
                *(float2*)&C[(size_t)(m0 + 8) * DM + n0] = make_float2(c2v, c3v);
            } else if (mode == 3) {
                // V: head-transposed store [b][h][d][s]
                __half* C = (__half*)Cout;
                const int b = m0 >> 11, ss = m0 & 2047;
                const size_t base0 =
                    ((size_t)(b * HH + (n0 >> 6)) * DKH + (n0 & 63)) * SEQ;
                const size_t base1 = base0 + SEQ;  // n0+1 same head (n0 even)
                C[base0 + ss]     = __float2half_rn(c0v);
                C[base1 + ss]     = __float2half_rn(c1v);
                C[base0 + ss + 8] = __float2half_rn(c2v);
                C[base1 + ss + 8] = __float2half_rn(c3v);
            } else {
                const float sc = (mode == 2) ? 0.125f : 1.0f;
                __half* C = (__half*)Cout;
                *(uint32_t*)&C[(size_t)m0 * DM + n0] =
                    packh2(c0v * sc, c1v * sc);
                *(uint32_t*)&C[(size_t)(m0 + 8) * DM + n0] =
                    packh2(c2v * sc, c3v * sc);
            }
        }
    }
}

struct QKVArgs {
    const __half* A[3];
    const __half* B[3];
    void*         C[3];
};

__global__ __launch_bounds__(256)
void gemm_qkv_kernel(QKVArgs a)
{
    const int z = blockIdx.z;
    // z: 0=Q (mode2), 1=K (mode1), 2=V (mode3 transposed)
    gemm_h_body(a.A[z], a.B[z], a.C[z], z == 0 ? 2 : (z == 1 ? 1 : 3));
}

__global__ __launch_bounds__(256)
void gemm_o_kernel(const __half* __restrict__ A,
                   const __half* __restrict__ B,
                   float* __restrict__ C)
{
    gemm_h_body(A, B, C, 0);
}

// ---------------------------------------------------------------------------
// fp16 flash attention v5. Block = (b*H+h, 128 q-rows), 128 threads = 4 warps,
// warp = 32 q rows (2 m16 frags). K tile natural [kv][d], V tile [d][kv]
// (from head-transposed g_Vt) — both 64x64 halfs, XOR-swizzled, all fragment
// loads contiguous half2 and bank-conflict-free. PV A-fragment comes straight
// from the S C-fragment (no shuffles). Per-lane l partials (v4 scheme).
// ---------------------------------------------------------------------------
#define QTILE 128
#define NKV   (SEQ / 64)     // 32 kv tiles
#define AT_TILE 8192         // 64*64 halfs = 8KB
#define ATTN_SMEM (4 * AT_TILE)  // K[2] + V[2] = 32KB

__global__ __launch_bounds__(128)
void attn_f16_kernel(const __half* __restrict__ Q,
                     const __half* __restrict__ K,
                     const __half* __restrict__ Vt,
                     __half* __restrict__ ctx)
{
    const int bh = blockIdx.x;
    const int b  = bh / HH;
    const int h  = bh % HH;
    const int q0 = blockIdx.y * QTILE;

    extern __shared__ __align__(128) __half smh[];
    const uint32_t smem_u = (uint32_t)__cvta_generic_to_shared(smh);

    const int tid  = threadIdx.x;
    const int lane = tid & 31;
    const int warp = tid >> 5;
    const int wq   = warp * 32;
    const int g    = lane >> 2;
    const int tg   = lane & 3;

    const __half* Kbase = K + (size_t)b * SEQ * DM + h * DKH;
    const __half* Vtb   = Vt + (size_t)(b * HH + h) * DKH * SEQ;

    // load K tile (natural [kv][d]) and V tile ([d][kv]) for kv-block t
    auto prefetch = [&](int t, int buf) {
#pragma unroll
        for (int i = 0; i < 8; i++) {
            int idx = tid + i * 128;        // 0..1023
            int arr = idx >> 9;             // 0 = K, 1 = Vt
            int r   = (idx >> 3) & 63;
            int u   = idx & 7;
            uint32_t off = r * 128 + ((u ^ (r & 7)) << 4);
            if (arr == 0)
                cp16(smem_u + buf * AT_TILE + off,
                     Kbase + (size_t)(t * 64 + r) * DM + u * 8);
            else
                cp16(smem_u + 2 * AT_TILE + buf * AT_TILE + off,
                     Vtb + (size_t)r * SEQ + t * 64 + u * 8);
        }
        cp_commit();
    };

    // hoist Q fragments (pre-scaled fp16) straight from gmem: 32 regs
    uint32_t qa[2][4][4];
    {
        const __half* Qb = Q + ((size_t)b * SEQ + q0 + wq) * DM + h * DKH;
#pragma unroll
        for (int mf = 0; mf < 2; mf++)
#pragma unroll
            for (int j = 0; j < 4; j++) {
                const __half* r0 = Qb + (size_t)(mf * 16 + g) * DM + j * 16 + 2 * tg;
                const __half* r1 = r0 + (size_t)8 * DM;
                qa[mf][j][0] = *(const uint32_t*)r0;
                qa[mf][j][1] = *(const uint32_t*)r1;
                qa[mf][j][2] = *(const uint32_t*)(r0 + 8);
                qa[mf][j][3] = *(const uint32_t*)(r1 + 8);
            }
    }

    prefetch(0, 0);

    float m_r[2][2], l_r[2][2];     // per-lane l partials
    float Oacc[2][8][4];
#pragma unroll
    for (int mf = 0; mf < 2; mf++) {
        m_r[mf][0] = -INFINITY; m_r[mf][1] = -INFINITY;
        l_r[mf][0] = 0.f;       l_r[mf][1] = 0.f;
#pragma unroll
        for (int nf = 0; nf < 8; nf++)
#pragma unroll
            for (int c = 0; c < 4; c++) Oacc[mf][nf][c] = 0.f;
    }

    int buf = 0;
    for (int t = 0; t < NKV; t++) {
        if (t + 1 < NKV) prefetch(t + 1, buf ^ 1);
        else             cp_commit();
        cp_wait<1>();
        __syncthreads();

        const __half* kt = smh + buf * (AT_TILE / 2);
        const __half* vt = smh + (2 + buf) * (AT_TILE / 2);

#pragma unroll
        for (int kc = 0; kc < 2; kc++) {    // two 32-kv chunks
            // ---- S = Q @ K^T (warp: 32q x 32kv) ----
            float sacc[2][4][4];
#pragma unroll
            for (int mf = 0; mf < 2; mf++)
#pragma unroll
                for (int nf = 0; nf < 4; nf++)
#pragma unroll
                    for (int c = 0; c < 4; c++) sacc[mf][nf][c] = 0.f;

#pragma unroll
            for (int j = 0; j < 4; j++) {   // d k16-steps
                const int c0 = j * 16 + 2 * tg;
#pragma unroll
                for (int nf = 0; nf < 4; nf++) {
                    const int rn = kc * 32 + nf * 8 + g;
                    uint32_t bf[2] = {
                        *(const uint32_t*)(kt + hx(rn, c0)),
                        *(const uint32_t*)(kt + hx(rn, c0 + 8))
                    };
                    mma_f16(sacc[0][nf], qa[0][j], bf);
                    mma_f16(sacc[1][nf], qa[1][j], bf);
                }
            }

            // ---- online softmax per m-fragment (rows g, g+8) ----
#pragma unroll
            for (int mf = 0; mf < 2; mf++) {
                float mx0 = -INFINITY, mx1 = -INFINITY;
#pragma unroll
                for (int nf = 0; nf < 4; nf++) {
                    mx0 = fmaxf(mx0, fmaxf(sacc[mf][nf][0], sacc[mf][nf][1]));
                    mx1 = fmaxf(mx1, fmaxf(sacc[mf][nf][2], sacc[mf][nf][3]));
                }
                mx0 = fmaxf(mx0, __shfl_xor_sync(0xffffffffu, mx0, 1));
                mx0 = fmaxf(mx0, __shfl_xor_sync(0xffffffffu, mx0, 2));
                mx1 = fmaxf(mx1, __shfl_xor_sync(0xffffffffu, mx1, 1));
                mx1 = fmaxf(mx1, __shfl_xor_sync(0xffffffffu, mx1, 2));

                const float mn0 = fmaxf(m_r[mf][0], mx0);
                const float mn1 = fmaxf(m_r[mf][1], mx1);
                const float al0 = __expf(m_r[mf][0] - mn0);
                const float al1 = __expf(m_r[mf][1] - mn1);

                float s0 = 0.f, s1 = 0.f;
#pragma unroll
                for (int nf = 0; nf < 4; nf++) {
                    float p0 = __expf(sacc[mf][nf][0] - mn0);
                    float p1 = __expf(sacc[mf][nf][1] - mn0);
                    float p2 = __expf(sacc[mf][nf][2] - mn1);
                    float p3 = __expf(sacc[mf][nf][3] - mn1);
                    sacc[mf][nf][0] = p0; sacc[mf][nf][1] = p1;
                    sacc[mf][nf][2] = p2; sacc[mf][nf][3] = p3;
                    s0 += p0 + p1;
                    s1 += p2 + p3;
                }
                m_r[mf][0] = mn0; m_r[mf][1] = mn1;
                l_r[mf][0] = l_r[mf][0] * al0 + s0;
                l_r[mf][1] = l_r[mf][1] * al1 + s1;

#pragma unroll
                for (int nf = 0; nf < 8; nf++) {
                    Oacc[mf][nf][0] *= al0; Oacc[mf][nf][1] *= al0;
                    Oacc[mf][nf][2] *= al1; Oacc[mf][nf][3] *= al1;
                }
            }

            // ---- O += P @ V : A-frag = packed S C-frag (no shuffles) ----
#pragma unroll
            for (int j2 = 0; j2 < 2; j2++) {   // kv k16-steps within chunk
                uint32_t af[2][4];
#pragma unroll
                for (int mf = 0; mf < 2; mf++) {
                    af[mf][0] = packh2(sacc[mf][2 * j2][0],     sacc[mf][2 * j2][1]);
                    af[mf][1] = packh2(sacc[mf][2 * j2][2],     sacc[mf][2 * j2][3]);
                    af[mf][2] = packh2(sacc[mf][2 * j2 + 1][0], sacc[mf][2 * j2 + 1][1]);
                    af[mf][3] = packh2(sacc[mf][2 * j2 + 1][2], sacc[mf][2 * j2 + 1][3]);
                }
                const int k0 = kc * 32 + j2 * 16 + 2 * tg;
#pragma unroll
                for (int nf = 0; nf < 8; nf++) {
                    const int rd = nf * 8 + g;
                    uint32_t bf[2] = {
                        *(const uint32_t*)(vt + hx(rd, k0)),
                        *(const uint32_t*)(vt + hx(rd, k0 + 8))
                    };
                    mma_f16(Oacc[0][nf], af[0], bf);
                    mma_f16(Oacc[1][nf], af[1], bf);
                }
            }
        }

        __syncthreads();
        buf ^= 1;
    }

    // ---- epilogue: reduce l across quad, write fp16 ctx (natural) ----
#pragma unroll
    for (int mf = 0; mf < 2; mf++) {
        float l0 = l_r[mf][0], l1 = l_r[mf][1];
        l0 += __shfl_xor_sync(0xffffffffu, l0, 1);
        l0 += __shfl_xor_sync(0xffffffffu, l0, 2);
        l1 += __shfl_xor_sync(0xffffffffu, l1, 1);
        l1 += __shfl_xor_sync(0xffffffffu, l1, 2);
        const float inv0 = 1.f / l0;
        const float inv1 = 1.f / l1;
        __half* out = ctx + ((size_t)b * SEQ + q0 + wq + mf * 16) * DM + h * DKH;
#pragma unroll
        for (int nf = 0; nf < 8; nf++) {
            *(uint32_t*)&out[(size_t)g * DM + nf * 8 + tg * 2] =
                packh2(Oacc[mf][nf][0] * inv0, Oacc[mf][nf][1] * inv0);
            *(uint32_t*)&out[(size_t)(g + 8) * DM + nf * 8 + tg * 2] =
                packh2(Oacc[mf][nf][2] * inv1, Oacc[mf][nf][3] * inv1);
        }
    }
}

// ---------------------------------------------------------------------------
// Launch
// ---------------------------------------------------------------------------
extern "C" void kernel_launch(void* const* d_in, const int* in_sizes, int n_in,
                              void* d_out, int out_size)
{
    (void)in_sizes; (void)n_in; (void)out_size;
    const float* q  = (const float*)d_in[0];
    const float* k  = (const float*)d_in[1];
    const float* v  = (const float*)d_in[2];
    const float* Wq = (const float*)d_in[3];
    const float* Wk = (const float*)d_in[4];
    const float* Wv = (const float*)d_in[5];
    const float* Wo = (const float*)d_in[6];
    float* out = (float*)d_out;

    __half *hq, *hk, *hv, *hWq, *hWk, *hWv, *hWo;
    __half *gQ, *gK, *gVt, *gC;
    cudaGetSymbolAddress((void**)&hq,  h_q);
    cudaGetSymbolAddress((void**)&hk,  h_k);
    cudaGetSymbolAddress((void**)&hv,  h_v);
    cudaGetSymbolAddress((void**)&hWq, h_Wq);
    cudaGetSymbolAddress((void**)&hWk, h_Wk);
    cudaGetSymbolAddress((void**)&hWv, h_Wv);
    cudaGetSymbolAddress((void**)&hWo, h_Wo);
    cudaGetSymbolAddress((void**)&gQ,  g_Qh);
    cudaGetSymbolAddress((void**)&gK,  g_Kh);
    cudaGetSymbolAddress((void**)&gVt, g_Vt);
    cudaGetSymbolAddress((void**)&gC,  g_ctxh);

    static bool attr_set = false;
    if (!attr_set) {
        cudaFuncSetAttribute(attn_f16_kernel,
                             cudaFuncAttributeMaxDynamicSharedMemorySize, ATTN_SMEM);
        cudaFuncSetAttribute(gemm_qkv_kernel,
                             cudaFuncAttributeMaxDynamicSharedMemorySize, H_SMEM);
        cudaFuncSetAttribute(gemm_o_kernel,
                             cudaFuncAttributeMaxDynamicSharedMemorySize, H_SMEM);
        attr_set = true;
    }

    // ---- fused f32 -> f16 pre-convert (one launch, 7 tensors) ----
    const int n8_x = MTOT * DM / 8;   // 1M groups of 8
    const int n8_w = DM * DM / 8;     // 128K groups
    ConvArgs ca;
    ca.src[0] = (const float4*)q;  ca.dst[0] = (uint4*)hq;  ca.n8[0] = n8_x;
    ca.src[1] = (const float4*)k;  ca.dst[1] = (uint4*)hk;  ca.n8[1] = n8_x;
    ca.src[2] = (const float4*)v;  ca.dst[2] = (uint4*)hv;  ca.n8[2] = n8_x;
    ca.src[3] = (const float4*)Wq; ca.dst[3] = (uint4*)hWq; ca.n8[3] = n8_w;
    ca.src[4] = (const float4*)Wk; ca.dst[4] = (uint4*)hWk; ca.n8[4] = n8_w;
    ca.src[5] = (const float4*)Wv; ca.dst[5] = (uint4*)hWv; ca.n8[5] = n8_w;
    ca.src[6] = (const float4*)Wo; ca.dst[6] = (uint4*)hWo; ca.n8[6] = n8_w;
    dim3 cgrid((n8_x + 1023) / 1024, 7);
    conv_all_kernel<<<cgrid, 256>>>(ca);

    // ---- fused Q/K/V projections (fp16 tensor cores) ----
    QKVArgs qa;
    qa.A[0] = hq; qa.B[0] = hWq; qa.C[0] = gQ;    // Q: *0.125, f16
    qa.A[1] = hk; qa.B[1] = hWk; qa.C[1] = gK;    // K: f16 natural
    qa.A[2] = hv; qa.B[2] = hWv; qa.C[2] = gVt;   // V: f16 head-transposed
    dim3 qgrid(DM / 128, MTOT / 128, 3);
    gemm_qkv_kernel<<<qgrid, 256, H_SMEM>>>(qa);

    // ---- attention ----
    dim3 agrid(BATCH * HH, SEQ / QTILE);   // (64, 16)
    attn_f16_kernel<<<agrid, 128, ATTN_SMEM>>>(gQ, gK, gVt, gC);

    // ---- output projection ----
    dim3 ogrid(DM / 128, MTOT / 128);
    gemm_o_kernel<<<ogrid, 256, H_SMEM>>>(gC, hWo, out);
}

// round 12
// speedup vs baseline: 1.8217x; 1.0526x over previous
#include <cuda_runtime.h>
#include <cuda_fp16.h>
#include <math.h>
#include <stdint.h>

// Problem constants (fixed by the reference)
#define DM    1024
#define HH    16
#define DKH   64
#define BATCH 4
#define SEQ   2048
#define MTOT  (BATCH * SEQ)   // 8192

// ---------------------------------------------------------------------------
// Scratch (no allocations allowed -> __device__ globals)
// ---------------------------------------------------------------------------
// fp16 copies of inputs
__device__ __align__(128) __half h_q[(size_t)MTOT * DM];
__device__ __align__(128) __half h_k[(size_t)MTOT * DM];
__device__ __align__(128) __half h_v[(size_t)MTOT * DM];
__device__ __align__(128) __half h_Wq[(size_t)DM * DM];
__device__ __align__(128) __half h_Wk[(size_t)DM * DM];
__device__ __align__(128) __half h_Wv[(size_t)DM * DM];
__device__ __align__(128) __half h_Wo[(size_t)DM * DM];
// projected tensors (fp16). g_Vt is head-transposed: [b][h][d][s]
__device__ __align__(128) __half g_Qh[(size_t)MTOT * DM];
__device__ __align__(128) __half g_Kh[(size_t)MTOT * DM];
__device__ __align__(128) __half g_Vt[(size_t)MTOT * DM];
__device__ __align__(128) __half g_ctxh[(size_t)MTOT * DM];

// ---------------------------------------------------------------------------
// Helpers
// ---------------------------------------------------------------------------
__device__ __forceinline__ uint32_t packh2(float lo, float hi) {
    __half2 h = __floats2half2_rn(lo, hi);
    return *reinterpret_cast<uint32_t*>(&h);
}

__device__ __forceinline__ void mma_f16(float (&d)[4],
                                        const uint32_t (&a)[4],
                                        const uint32_t (&b)[2]) {
    asm volatile(
        "mma.sync.aligned.m16n8k16.row.col.f32.f16.f16.f32 "
        "{%0,%1,%2,%3}, {%4,%5,%6,%7}, {%8,%9}, {%0,%1,%2,%3};"
        : "+f"(d[0]), "+f"(d[1]), "+f"(d[2]), "+f"(d[3])
        : "r"(a[0]), "r"(a[1]), "r"(a[2]), "r"(a[3]),
          "r"(b[0]), "r"(b[1]));
}

__device__ __forceinline__ void cp16(uint32_t dst_smem, const void* src) {
    asm volatile("cp.async.cg.shared.global [%0], [%1], 16;"
                 :: "r"(dst_smem), "l"(src));
}
__device__ __forceinline__ void cp_commit() {
    asm volatile("cp.async.commit_group;");
}
template <int N>
__device__ __forceinline__ void cp_wait() {
    asm volatile("cp.async.wait_group %0;" :: "n"(N));
}

// swizzled half-index for element (row, k) of a tile with 64-half (128B) rows
__device__ __forceinline__ int hx(int row, int k) {
    return row * 64 + (((k >> 3) ^ (row & 7)) << 3) + (k & 7);
}

// ---------------------------------------------------------------------------
// Fused f32 -> f16 pre-convert: one launch, grid.y selects tensor.
// ---------------------------------------------------------------------------
struct ConvArgs {
    const float4* src[7];
    uint4*        dst[7];
    int           n8[7];
};

__global__ __launch_bounds__(256)
void conv_all_kernel(ConvArgs a)
{
    const int seg = blockIdx.y;
    const float4* __restrict__ in = a.src[seg];
    uint4* __restrict__ out = a.dst[seg];
    const int n8 = a.n8[seg];
    int base = blockIdx.x * 1024 + threadIdx.x;
    if (base >= n8) return;
#pragma unroll
    for (int j = 0; j < 4; j++) {
        int i = base + j * 256;
        if (i < n8) {
            float4 v0 = in[2 * i];
            float4 v1 = in[2 * i + 1];
            out[i] = make_uint4(packh2(v0.x, v0.y), packh2(v0.z, v0.w),
                                packh2(v1.x, v1.y), packh2(v1.z, v1.w));
        }
    }
}

// ---------------------------------------------------------------------------
// fp16 cp.async pipelined GEMM NT: C[M,N] = A[M,K] * B[N,K]^T
// CTA tile 128x128, BK=64 halfs (128B rows), 3 stages (96KB), one sync/iter.
// __launch_bounds__(256, 2): 128-reg cap -> 2 CTAs/SM, 16 warps/SM to fill
// barrier + scoreboard gaps (MMA cover per barrier stays 128 — the R10
// confound removed). 8 warps (2m x 4n), warp tile 64x32, m16n8k16.
// mode: 0 = f32 natural store (O), 1 = f16 natural (K),
//       2 = f16 natural * 0.125 (Q), 3 = f16 head-transposed [b,h,d,s] (V).
// ---------------------------------------------------------------------------
#define HBK 64
#define HNST 3
#define HNKB (DM / HBK)                   // 16
#define H_ARR (128 * HBK * 2)             // 16KB per array per stage
#define H_STG (2 * H_ARR)                 // 32KB
#define H_SMEM (HNST * H_STG)             // 96KB

__device__ __forceinline__
void gemm_h_body(const __half* __restrict__ A,
                 const __half* __restrict__ B,
                 void* __restrict__ Cout, int mode)
{
    extern __shared__ __align__(128) __half smh[];
    const uint32_t smem_base = (uint32_t)__cvta_generic_to_shared(smh);

    const int tid = threadIdx.x;
    const int bn = blockIdx.x * 128;
    const int bm = blockIdx.y * 128;

    const int lane = tid & 31;
    const int wid  = tid >> 5;
    const int wm   = wid >> 2;          // 0..1
    const int wn   = wid & 3;           // 0..3
    const int g    = lane >> 2;         // 0..7
    const int tg   = lane & 3;          // 0..3

    float acc[4][4][4];
#pragma unroll
    for (int i = 0; i < 4; i++)
#pragma unroll
        for (int j = 0; j < 4; j++)
#pragma unroll
            for (int c = 0; c < 4; c++) acc[i][j][c] = 0.f;

    // fill one stage: A/B, 128 rows x 8 16B-units each, XOR swizzled
    auto fill = [&](int slot, int kb) {
        const uint32_t ab = smem_base + slot * H_STG;
        const uint32_t bb = ab + H_ARR;
        const __half* Ak = A + (size_t)bm * DM + kb * HBK;
        const __half* Bk = B + (size_t)bn * DM + kb * HBK;
#pragma unroll
        for (int i = 0; i < 4; i++) {
            int idx = tid + i * 256;        // 0..1023
            int row = idx >> 3;             // 0..127
            int u   = idx & 7;              // 16B unit in 128B row
            uint32_t off = row * 128 + ((u ^ (row & 7)) << 4);
            cp16(ab + off, Ak + (size_t)row * DM + u * 8);
            cp16(bb + off, Bk + (size_t)row * DM + u * 8);
        }
        cp_commit();
    };

    fill(0, 0);
    fill(1, 1);

    for (int s = 0; s < HNKB; s++) {
        const int slot = s % HNST;
        if (s < HNKB - 1) cp_wait<1>();
        else              cp_wait<0>();
        __syncthreads();

        if (s + 2 < HNKB) fill((s + 2) % HNST, s + 2);

        const __half* as = smh + (size_t)slot * (H_STG / 2);
        const __half* bs = as + H_ARR / 2;

#pragma unroll
        for (int j = 0; j < 4; j++) {       // k16 steps within BK=64
            uint32_t af[4][4];
            uint32_t bf[4][2];
            const int c0 = j * 16 + 2 * tg;
#pragma unroll
            for (int mf = 0; mf < 4; mf++) {
                const int r0 = wm * 64 + mf * 16 + g;
                af[mf][0] = *(const uint32_t*)(as + hx(r0,     c0));
                af[mf][1] = *(const uint32_t*)(as + hx(r0 + 8, c0));
                af[mf][2] = *(const uint32_t*)(as + hx(r0,     c0 + 8));
                af[mf][3] = *(const uint32_t*)(as + hx(r0 + 8, c0 + 8));
            }
#pragma unroll
            for (int nf = 0; nf < 4; nf++) {
                const int rn = wn * 32 + nf * 8 + g;
                bf[nf][0] = *(const uint32_t*)(bs + hx(rn, c0));
                bf[nf][1] = *(const uint32_t*)(bs + hx(rn, c0 + 8));
            }
#pragma unroll
            for (int mf = 0; mf < 4; mf++)
#pragma unroll
                for (int nf = 0; nf < 4; nf++)
                    mma_f16(acc[mf][nf], af[mf], bf[nf]);
        }
    }

    // ---- epilogue ----
#pragma unroll
    for (int mf = 0; mf < 4; mf++) {
#pragma unroll
        for (int nf = 0; nf < 4; nf++) {
            const int m0 = bm + wm * 64 + mf * 16 + g;
            const int n0 = bn + wn * 32 + nf * 8 + tg * 2;
            float c0v = acc[mf][nf][0], c1v = acc[mf][nf][1];
            float c2v = acc[mf][nf][2], c3v = acc[mf][nf][3];
            if (mode == 0) {
                float* C = (float*)Cout;
                *(float2*)&C[(size_t)m0 * DM + n0] = make_float2(c0v, c1v);
                *(float2*)&C[(size_t)(m0 + 8) * DM + n0] = make_float2(c2v, c3v);
            } else if (mode == 3) {
                // V: head-transposed store [b][h][d][s]
                __half* C = (__half*)Cout;
                const int b = m0 >> 11, ss = m0 & 2047;
                const size_t base0 =
                    ((size_t)(b * HH + (n0 >> 6)) * DKH + (n0 & 63)) * SEQ;
                const size_t base1 = base0 + SEQ;  // n0+1 same head (n0 even)
                C[base0 + ss]     = __float2half_rn(c0v);
                C[base1 + ss]     = __float2half_rn(c1v);
                C[base0 + ss + 8] = __float2half_rn(c2v);
                C[base1 + ss + 8] = __float2half_rn(c3v);
            } else {
                const float sc = (mode == 2) ? 0.125f : 1.0f;
                __half* C = (__half*)Cout;
                *(uint32_t*)&C[(size_t)m0 * DM + n0] =
                    packh2(c0v * sc, c1v * sc);
                *(uint32_t*)&C[(size_t)(m0 + 8) * DM + n0] =
                    packh2(c2v * sc, c3v * sc);
            }
        }
    }
}

struct QKVArgs {
    const __half* A[3];
    const __half* B[3];
    void*         C[3];
};

__global__ __launch_bounds__(256, 2)
void gemm_qkv_kernel(QKVArgs a)
{
    const int z = blockIdx.z;
    // z: 0=Q (mode2), 1=K (mode1), 2=V (mode3 transposed)
    gemm_h_body(a.A[z], a.B[z], a.C[z], z == 0 ? 2 : (z == 1 ? 1 : 3));
}

__global__ __launch_bounds__(256, 2)
void gemm_o_kernel(const __half* __restrict__ A,
                   const __half* __restrict__ B,
                   float* __restrict__ C)
{
    gemm_h_body(A, B, C, 0);
}

// ---------------------------------------------------------------------------
// fp16 flash attention v5 (R11, verified): K natural, V head-transposed,
// PV A-fragment packed straight from S C-fragment, per-lane l partials.
// ---------------------------------------------------------------------------
#define QTILE 128
#define NKV   (SEQ / 64)     // 32 kv tiles
#define AT_TILE 8192         // 64*64 halfs = 8KB
#define ATTN_SMEM (4 * AT_TILE)  // K[2] + V[2] = 32KB

__global__ __launch_bounds__(128)
void attn_f16_kernel(const __half* __restrict__ Q,
                     const __half* __restrict__ K,
                     const __half* __restrict__ Vt,
                     __half* __restrict__ ctx)
{
    const int bh = blockIdx.x;
    const int b  = bh / HH;
    const int h  = bh % HH;
    const int q0 = blockIdx.y * QTILE;

    extern __shared__ __align__(128) __half smh[];
    const uint32_t smem_u = (uint32_t)__cvta_generic_to_shared(smh);

    const int tid  = threadIdx.x;
    const int lane = tid & 31;
    const int warp = tid >> 5;
    const int wq   = warp * 32;
    const int g    = lane >> 2;
    const int tg   = lane & 3;

    const __half* Kbase = K + (size_t)b * SEQ * DM + h * DKH;
    const __half* Vtb   = Vt + (size_t)(b * HH + h) * DKH * SEQ;

    auto prefetch = [&](int t, int buf) {
#pragma unroll
        for (int i = 0; i < 8; i++) {
            int idx = tid + i * 128;        // 0..1023
            int arr = idx >> 9;             // 0 = K, 1 = Vt
            int r   = (idx >> 3) & 63;
            int u   = idx & 7;
            uint32_t off = r * 128 + ((u ^ (r & 7)) << 4);
            if (arr == 0)
                cp16(smem_u + buf * AT_TILE + off,
                     Kbase + (size_t)(t * 64 + r) * DM + u * 8);
            else
                cp16(smem_u + 2 * AT_TILE + buf * AT_TILE + off,
                     Vtb + (size_t)r * SEQ + t * 64 + u * 8);
        }
        cp_commit();
    };

    // hoist Q fragments (pre-scaled fp16) straight from gmem: 32 regs
    uint32_t qa[2][4][4];
    {
        const __half* Qb = Q + ((size_t)b * SEQ + q0 + wq) * DM + h * DKH;
#pragma unroll
        for (int mf = 0; mf < 2; mf++)
#pragma unroll
            for (int j = 0; j < 4; j++) {
                const __half* r0 = Qb + (size_t)(mf * 16 + g) * DM + j * 16 + 2 * tg;
                const __half* r1 = r0 + (size_t)8 * DM;
                qa[mf][j][0] = *(const uint32_t*)r0;
                qa[mf][j][1] = *(const uint32_t*)r1;
                qa[mf][j][2] = *(const uint32_t*)(r0 + 8);
                qa[mf][j][3] = *(const uint32_t*)(r1 + 8);
            }
    }

    prefetch(0, 0);

    float m_r[2][2], l_r[2][2];     // per-lane l partials
    float Oacc[2][8][4];
#pragma unroll
    for (int mf = 0; mf < 2; mf++) {
        m_r[mf][0] = -INFINITY; m_r[mf][1] = -INFINITY;
        l_r[mf][0] = 0.f;       l_r[mf][1] = 0.f;
#pragma unroll
        for (int nf = 0; nf < 8; nf++)
#pragma unroll
            for (int c = 0; c < 4; c++) Oacc[mf][nf][c] = 0.f;
    }

    int buf = 0;
    for (int t = 0; t < NKV; t++) {
        if (t + 1 < NKV) prefetch(t + 1, buf ^ 1);
        else             cp_commit();
        cp_wait<1>();
        __syncthreads();

        const __half* kt = smh + buf * (AT_TILE / 2);
        const __half* vt = smh + (2 + buf) * (AT_TILE / 2);

#pragma unroll
        for (int kc = 0; kc < 2; kc++) {    // two 32-kv chunks
            // ---- S = Q @ K^T (warp: 32q x 32kv) ----
            float sacc[2][4][4];
#pragma unroll
            for (int mf = 0; mf < 2; mf++)
#pragma unroll
                for (int nf = 0; nf < 4; nf++)
#pragma unroll
                    for (int c = 0; c < 4; c++) sacc[mf][nf][c] = 0.f;

#pragma unroll
            for (int j = 0; j < 4; j++) {   // d k16-steps
                const int c0 = j * 16 + 2 * tg;
#pragma unroll
                for (int nf = 0; nf < 4; nf++) {
                    const int rn = kc * 32 + nf * 8 + g;
                    uint32_t bf[2] = {
                        *(const uint32_t*)(kt + hx(rn, c0)),
                        *(const uint32_t*)(kt + hx(rn, c0 + 8))
                    };
                    mma_f16(sacc[0][nf], qa[0][j], bf);
                    mma_f16(sacc[1][nf], qa[1][j], bf);
                }
            }

            // ---- online softmax per m-fragment (rows g, g+8) ----
#pragma unroll
            for (int mf = 0; mf < 2; mf++) {
                float mx0 = -INFINITY, mx1 = -INFINITY;
#pragma unroll
                for (int nf = 0; nf < 4; nf++) {
                    mx0 = fmaxf(mx0, fmaxf(sacc[mf][nf][0], sacc[mf][nf][1]));
                    mx1 = fmaxf(mx1, fmaxf(sacc[mf][nf][2], sacc[mf][nf][3]));
                }
                mx0 = fmaxf(mx0, __shfl_xor_sync(0xffffffffu, mx0, 1));
                mx0 = fmaxf(mx0, __shfl_xor_sync(0xffffffffu, mx0, 2));
                mx1 = fmaxf(mx1, __shfl_xor_sync(0xffffffffu, mx1, 1));
                mx1 = fmaxf(mx1, __shfl_xor_sync(0xffffffffu, mx1, 2));

                const float mn0 = fmaxf(m_r[mf][0], mx0);
                const float mn1 = fmaxf(m_r[mf][1], mx1);
                const float al0 = __expf(m_r[mf][0] - mn0);
                const float al1 = __expf(m_r[mf][1] - mn1);

                float s0 = 0.f, s1 = 0.f;
#pragma unroll
                for (int nf = 0; nf < 4; nf++) {
                    float p0 = __expf(sacc[mf][nf][0] - mn0);
                    float p1 = __expf(sacc[mf][nf][1] - mn0);
                    float p2 = __expf(sacc[mf][nf][2] - mn1);
                    float p3 = __expf(sacc[mf][nf][3] - mn1);
                    sacc[mf][nf][0] = p0; sacc[mf][nf][1] = p1;
                    sacc[mf][nf][2] = p2; sacc[mf][nf][3] = p3;
                    s0 += p0 + p1;
                    s1 += p2 + p3;
                }
                m_r[mf][0] = mn0; m_r[mf][1] = mn1;
                l_r[mf][0] = l_r[mf][0] * al0 + s0;
                l_r[mf][1] = l_r[mf][1] * al1 + s1;

#pragma unroll
                for (int nf = 0; nf < 8; nf++) {
                    Oacc[mf][nf][0] *= al0; Oacc[mf][nf][1] *= al0;
                    Oacc[mf][nf][2] *= al1; Oacc[mf][nf][3] *= al1;
                }
            }

            // ---- O += P @ V : A-frag = packed S C-frag (no shuffles) ----
#pragma unroll
            for (int j2 = 0; j2 < 2; j2++) {   // kv k16-steps within chunk
                uint32_t af[2][4];
#pragma unroll
                for (int mf = 0; mf < 2; mf++) {
                    af[mf][0] = packh2(sacc[mf][2 * j2][0],     sacc[mf][2 * j2][1]);
                    af[mf][1] = packh2(sacc[mf][2 * j2][2],     sacc[mf][2 * j2][3]);
                    af[mf][2] = packh2(sacc[mf][2 * j2 + 1][0], sacc[mf][2 * j2 + 1][1]);
                    af[mf][3] = packh2(sacc[mf][2 * j2 + 1][2], sacc[mf][2 * j2 + 1][3]);
                }
                const int k0 = kc * 32 + j2 * 16 + 2 * tg;
#pragma unroll
                for (int nf = 0; nf < 8; nf++) {
                    const int rd = nf * 8 + g;
                    uint32_t bf[2] = {
                        *(const uint32_t*)(vt + hx(rd, k0)),
                        *(const uint32_t*)(vt + hx(rd, k0 + 8))
                    };
                    mma_f16(Oacc[0][nf], af[0], bf);
                    mma_f16(Oacc[1][nf], af[1], bf);
                }
            }
        }

        __syncthreads();
        buf ^= 1;
    }

    // ---- epilogue: reduce l across quad, write fp16 ctx (natural) ----
#pragma unroll
    for (int mf = 0; mf < 2; mf++) {
        float l0 = l_r[mf][0], l1 = l_r[mf][1];
        l0 += __shfl_xor_sync(0xffffffffu, l0, 1);
        l0 += __shfl_xor_sync(0xffffffffu, l0, 2);
        l1 += __shfl_xor_sync(0xffffffffu, l1, 1);
        l1 += __shfl_xor_sync(0xffffffffu, l1, 2);
        const float inv0 = 1.f / l0;
        const float inv1 = 1.f / l1;
        __half* out = ctx + ((size_t)b * SEQ + q0 + wq + mf * 16) * DM + h * DKH;
#pragma unroll
        for (int nf = 0; nf < 8; nf++) {
            *(uint32_t*)&out[(size_t)g * DM + nf * 8 + tg * 2] =
                packh2(Oacc[mf][nf][0] * inv0, Oacc[mf][nf][1] * inv0);
            *(uint32_t*)&out[(size_t)(g + 8) * DM + nf * 8 + tg * 2] =
                packh2(Oacc[mf][nf][2] * inv1, Oacc[mf][nf][3] * inv1);
        }
    }
}

// ---------------------------------------------------------------------------
// Launch
// ---------------------------------------------------------------------------
extern "C" void kernel_launch(void* const* d_in, const int* in_sizes, int n_in,
                              void* d_out, int out_size)
{
    (void)in_sizes; (void)n_in; (void)out_size;
    const float* q  = (const float*)d_in[0];
    const float* k  = (const float*)d_in[1];
    const float* v  = (const float*)d_in[2];
    const float* Wq = (const float*)d_in[3];
    const float* Wk = (const float*)d_in[4];
    const float* Wv = (const float*)d_in[5];
    const float* Wo = (const float*)d_in[6];
    float* out = (float*)d_out;

    __half *hq, *hk, *hv, *hWq, *hWk, *hWv, *hWo;
    __half *gQ, *gK, *gVt, *gC;
    cudaGetSymbolAddress((void**)&hq,  h_q);
    cudaGetSymbolAddress((void**)&hk,  h_k);
    cudaGetSymbolAddress((void**)&hv,  h_v);
    cudaGetSymbolAddress((void**)&hWq, h_Wq);
    cudaGetSymbolAddress((void**)&hWk, h_Wk);
    cudaGetSymbolAddress((void**)&hWv, h_Wv);
    cudaGetSymbolAddress((void**)&hWo, h_Wo);
    cudaGetSymbolAddress((void**)&gQ,  g_Qh);
    cudaGetSymbolAddress((void**)&gK,  g_Kh);
    cudaGetSymbolAddress((void**)&gVt, g_Vt);
    cudaGetSymbolAddress((void**)&gC,  g_ctxh);

    static bool attr_set = false;
    if (!attr_set) {
        cudaFuncSetAttribute(attn_f16_kernel,
                             cudaFuncAttributeMaxDynamicSharedMemorySize, ATTN_SMEM);
        cudaFuncSetAttribute(gemm_qkv_kernel,
                             cudaFuncAttributeMaxDynamicSharedMemorySize, H_SMEM);
        cudaFuncSetAttribute(gemm_o_kernel,
                             cudaFuncAttributeMaxDynamicSharedMemorySize, H_SMEM);
        attr_set = true;
    }

    // ---- fused f32 -> f16 pre-convert (one launch, 7 tensors) ----
    const int n8_x = MTOT * DM / 8;   // 1M groups of 8
    const int n8_w = DM * DM / 8;     // 128K groups
    ConvArgs ca;
    ca.src[0] = (const float4*)q;  ca.dst[0] = (uint4*)hq;  ca.n8[0] = n8_x;
    ca.src[1] = (const float4*)k;  ca.dst[1] = (uint4*)hk;  ca.n8[1] = n8_x;
    ca.src[2] = (const float4*)v;  ca.dst[2] = (uint4*)hv;  ca.n8[2] = n8_x;
    ca.src[3] = (const float4*)Wq; ca.dst[3] = (uint4*)hWq; ca.n8[3] = n8_w;
    ca.src[4] = (const float4*)Wk; ca.dst[4] = (uint4*)hWk; ca.n8[4] = n8_w;
    ca.src[5] = (const float4*)Wv; ca.dst[5] = (uint4*)hWv; ca.n8[5] = n8_w;
    ca.src[6] = (const float4*)Wo; ca.dst[6] = (uint4*)hWo; ca.n8[6] = n8_w;
    dim3 cgrid((n8_x + 1023) / 1024, 7);
    conv_all_kernel<<<cgrid, 256>>>(ca);

    // ---- fused Q/K/V projections (fp16 tensor cores) ----
    QKVArgs qa;
    qa.A[0] = hq; qa.B[0] = hWq; qa.C[0] = gQ;    // Q: *0.125, f16
    qa.A[1] = hk; qa.B[1] = hWk; qa.C[1] = gK;    // K: f16 natural
    qa.A[2] = hv; qa.B[2] = hWv; qa.C[2] = gVt;   // V: f16 head-transposed
    dim3 qgrid(DM / 128, MTOT / 128, 3);
    gemm_qkv_kernel<<<qgrid, 256, H_SMEM>>>(qa);

    // ---- attention ----
    dim3 agrid(BATCH * HH, SEQ / QTILE);   // (64, 16)
    attn_f16_kernel<<<agrid, 128, ATTN_SMEM>>>(gQ, gK, gVt, gC);

    // ---- output projection ----
    dim3 ogrid(DM / 128, MTOT / 128);
    gemm_o_kernel<<<ogrid, 256, H_SMEM>>>(gC, hWo, out);
}

// round 13
// speedup vs baseline: 1.8733x; 1.0283x over previous
#include <cuda_runtime.h>
#include <cuda_fp16.h>
#include <math.h>
#include <stdint.h>

// Problem constants (fixed by the reference)
#define DM    1024
#define HH    16
#define DKH   64
#define BATCH 4
#define SEQ   2048
#define MTOT  (BATCH * SEQ)   // 8192

// ---------------------------------------------------------------------------
// Scratch (no allocations allowed -> __device__ globals)
// ---------------------------------------------------------------------------
__device__ __align__(128) __half h_q[(size_t)MTOT * DM];
__device__ __align__(128) __half h_k[(size_t)MTOT * DM];
__device__ __align__(128) __half h_v[(size_t)MTOT * DM];
__device__ __align__(128) __half h_Wq[(size_t)DM * DM];
__device__ __align__(128) __half h_Wk[(size_t)DM * DM];
__device__ __align__(128) __half h_Wv[(size_t)DM * DM];
__device__ __align__(128) __half h_Wo[(size_t)DM * DM];
// projected tensors (fp16). g_Vt is head-transposed: [b][h][d][s]
__device__ __align__(128) __half g_Qh[(size_t)MTOT * DM];
__device__ __align__(128) __half g_Kh[(size_t)MTOT * DM];
__device__ __align__(128) __half g_Vt[(size_t)MTOT * DM];
__device__ __align__(128) __half g_ctxh[(size_t)MTOT * DM];

// ---------------------------------------------------------------------------
// Helpers
// ---------------------------------------------------------------------------
__device__ __forceinline__ uint32_t packh2(float lo, float hi) {
    __half2 h = __floats2half2_rn(lo, hi);
    return *reinterpret_cast<uint32_t*>(&h);
}

__device__ __forceinline__ void mma_f16(float (&d)[4],
                                        const uint32_t (&a)[4],
                                        const uint32_t (&b)[2]) {
    asm volatile(
        "mma.sync.aligned.m16n8k16.row.col.f32.f16.f16.f32 "
        "{%0,%1,%2,%3}, {%4,%5,%6,%7}, {%8,%9}, {%0,%1,%2,%3};"
        : "+f"(d[0]), "+f"(d[1]), "+f"(d[2]), "+f"(d[3])
        : "r"(a[0]), "r"(a[1]), "r"(a[2]), "r"(a[3]),
          "r"(b[0]), "r"(b[1]));
}

__device__ __forceinline__ void ldsm_x4(uint32_t (&r)[4], uint32_t addr) {
    asm volatile(
        "ldmatrix.sync.aligned.m8n8.x4.shared.b16 {%0,%1,%2,%3}, [%4];"
        : "=r"(r[0]), "=r"(r[1]), "=r"(r[2]), "=r"(r[3]) : "r"(addr));
}

__device__ __forceinline__ void cp16(uint32_t dst_smem, const void* src) {
    asm volatile("cp.async.cg.shared.global [%0], [%1], 16;"
                 :: "r"(dst_smem), "l"(src));
}
__device__ __forceinline__ void cp_commit() {
    asm volatile("cp.async.commit_group;");
}
template <int N>
__device__ __forceinline__ void cp_wait() {
    asm volatile("cp.async.wait_group %0;" :: "n"(N));
}

// swizzled half-index for element (row, k) of a tile with 64-half (128B) rows
__device__ __forceinline__ int hx(int row, int k) {
    return row * 64 + (((k >> 3) ^ (row & 7)) << 3) + (k & 7);
}

// ---------------------------------------------------------------------------
// Fused f32 -> f16 pre-convert: one launch, grid.y selects tensor.
// ---------------------------------------------------------------------------
struct ConvArgs {
    const float4* src[7];
    uint4*        dst[7];
    int           n8[7];
};

__global__ __launch_bounds__(256)
void conv_all_kernel(ConvArgs a)
{
    const int seg = blockIdx.y;
    const float4* __restrict__ in = a.src[seg];
    uint4* __restrict__ out = a.dst[seg];
    const int n8 = a.n8[seg];
    int base = blockIdx.x * 1024 + threadIdx.x;
    if (base >= n8) return;
#pragma unroll
    for (int j = 0; j < 4; j++) {
        int i = base + j * 256;
        if (i < n8) {
            float4 v0 = in[2 * i];
            float4 v1 = in[2 * i + 1];
            out[i] = make_uint4(packh2(v0.x, v0.y), packh2(v0.z, v0.w),
                                packh2(v1.x, v1.y), packh2(v1.z, v1.w));
        }
    }
}

// ---------------------------------------------------------------------------
// fp16 cp.async pipelined GEMM NT with ldmatrix fragment loads.
// CTA tile 128x128, BK=64 halfs, 3 stages (96KB), one sync/iter, 2 CTAs/SM.
// Per k16 step: 4 LDSM.x4 (A) + 2 LDSM.x4 (B) instead of 24 LDS.32.
// mode: 0 = f32 natural store (O), 1 = f16 natural (K),
//       2 = f16 natural * 0.125 (Q), 3 = f16 head-transposed [b,h,d,s] (V).
// ---------------------------------------------------------------------------
#define HBK 64
#define HNST 3
#define HNKB (DM / HBK)                   // 16
#define H_ARR (128 * HBK * 2)             // 16KB per array per stage
#define H_STG (2 * H_ARR)                 // 32KB
#define H_SMEM (HNST * H_STG)             // 96KB

__device__ __forceinline__
void gemm_h_body(const __half* __restrict__ A,
                 const __half* __restrict__ B,
                 void* __restrict__ Cout, int mode)
{
    extern __shared__ __align__(128) __half smh[];
    const uint32_t smem_base = (uint32_t)__cvta_generic_to_shared(smh);

    const int tid = threadIdx.x;
    const int bn = blockIdx.x * 128;
    const int bm = blockIdx.y * 128;

    const int lane = tid & 31;
    const int wid  = tid >> 5;
    const int wm   = wid >> 2;          // 0..1
    const int wn   = wid & 3;           // 0..3
    const int g    = lane >> 2;         // 0..7
    const int tg   = lane & 3;          // 0..3
    const int lrow  = lane & 15;        // ldmatrix row lane
    const int lcol8 = (lane >> 4) * 8;  // ldmatrix col-half offset

    float acc[4][4][4];
#pragma unroll
    for (int i = 0; i < 4; i++)
#pragma unroll
        for (int j = 0; j < 4; j++)
#pragma unroll
            for (int c = 0; c < 4; c++) acc[i][j][c] = 0.f;

    auto fill = [&](int slot, int kb) {
        const uint32_t ab = smem_base + slot * H_STG;
        const uint32_t bb = ab + H_ARR;
        const __half* Ak = A + (size_t)bm * DM + kb * HBK;
        const __half* Bk = B + (size_t)bn * DM + kb * HBK;
#pragma unroll
        for (int i = 0; i < 4; i++) {
            int idx = tid + i * 256;        // 0..1023
            int row = idx >> 3;             // 0..127
            int u   = idx & 7;              // 16B unit in 128B row
            uint32_t off = row * 128 + ((u ^ (row & 7)) << 4);
            cp16(ab + off, Ak + (size_t)row * DM + u * 8);
            cp16(bb + off, Bk + (size_t)row * DM + u * 8);
        }
        cp_commit();
    };

    fill(0, 0);
    fill(1, 1);

    for (int s = 0; s < HNKB; s++) {
        const int slot = s % HNST;
        if (s < HNKB - 1) cp_wait<1>();
        else              cp_wait<0>();
        __syncthreads();

        if (s + 2 < HNKB) fill((s + 2) % HNST, s + 2);

        const uint32_t a_sm = smem_base + slot * H_STG;
        const uint32_t b_sm = a_sm + H_ARR;

#pragma unroll
        for (int j = 0; j < 4; j++) {       // k16 steps within BK=64
            const int c0 = j * 16 + lcol8;
            uint32_t af[4][4];
            uint32_t bf[4][2];
#pragma unroll
            for (int mf = 0; mf < 4; mf++)
                ldsm_x4(af[mf], a_sm + 2 * hx(wm * 64 + mf * 16 + lrow, c0));
#pragma unroll
            for (int np = 0; np < 2; np++) {
                uint32_t t[4];
                ldsm_x4(t, b_sm + 2 * hx(wn * 32 + np * 16 + lrow, c0));
                bf[2 * np][0]     = t[0];
                bf[2 * np + 1][0] = t[1];
                bf[2 * np][1]     = t[2];
                bf[2 * np + 1][1] = t[3];
            }
#pragma unroll
            for (int mf = 0; mf < 4; mf++)
#pragma unroll
                for (int nf = 0; nf < 4; nf++)
                    mma_f16(acc[mf][nf], af[mf], bf[nf]);
        }
    }

    // ---- epilogue ----
#pragma unroll
    for (int mf = 0; mf < 4; mf++) {
#pragma unroll
        for (int nf = 0; nf < 4; nf++) {
            const int m0 = bm + wm * 64 + mf * 16 + g;
            const int n0 = bn + wn * 32 + nf * 8 + tg * 2;
            float c0v = acc[mf][nf][0], c1v = acc[mf][nf][1];
            float c2v = acc[mf][nf][2], c3v = acc[mf][nf][3];
            if (mode == 0) {
                float* C = (float*)Cout;
                *(float2*)&C[(size_t)m0 * DM + n0] = make_float2(c0v, c1v);
                *(float2*)&C[(size_t)(m0 + 8) * DM + n0] = make_float2(c2v, c3v);
            } else if (mode == 3) {
                __half* C = (__half*)Cout;
                const int b = m0 >> 11, ss = m0 & 2047;
                const size_t base0 =
                    ((size_t)(b * HH + (n0 >> 6)) * DKH + (n0 & 63)) * SEQ;
                const size_t base1 = base0 + SEQ;
                C[base0 + ss]     = __float2half_rn(c0v);
                C[base1 + ss]     = __float2half_rn(c1v);
                C[base0 + ss + 8] = __float2half_rn(c2v);
                C[base1 + ss + 8] = __float2half_rn(c3v);
            } else {
                const float sc = (mode == 2) ? 0.125f : 1.0f;
                __half* C = (__half*)Cout;
                *(uint32_t*)&C[(size_t)m0 * DM + n0] =
                    packh2(c0v * sc, c1v * sc);
                *(uint32_t*)&C[(size_t)(m0 + 8) * DM + n0] =
                    packh2(c2v * sc, c3v * sc);
            }
        }
    }
}

struct QKVArgs {
    const __half* A[3];
    const __half* B[3];
    void*         C[3];
};

__global__ __launch_bounds__(256, 2)
void gemm_qkv_kernel(QKVArgs a)
{
    const int z = blockIdx.z;
    gemm_h_body(a.A[z], a.B[z], a.C[z], z == 0 ? 2 : (z == 1 ? 1 : 3));
}

__global__ __launch_bounds__(256, 2)
void gemm_o_kernel(const __half* __restrict__ A,
                   const __half* __restrict__ B,
                   float* __restrict__ C)
{
    gemm_h_body(A, B, C, 0);
}

// ---------------------------------------------------------------------------
// fp16 flash attention v6: v5 + ldmatrix for K and V fragment loads.
// ---------------------------------------------------------------------------
#define QTILE 128
#define NKV   (SEQ / 64)     // 32 kv tiles
#define AT_TILE 8192         // 64*64 halfs = 8KB
#define ATTN_SMEM (4 * AT_TILE)  // K[2] + V[2] = 32KB

__global__ __launch_bounds__(128)
void attn_f16_kernel(const __half* __restrict__ Q,
                     const __half* __restrict__ K,
                     const __half* __restrict__ Vt,
                     __half* __restrict__ ctx)
{
    const int bh = blockIdx.x;
    const int b  = bh / HH;
    const int h  = bh % HH;
    const int q0 = blockIdx.y * QTILE;

    extern __shared__ __align__(128) __half smh[];
    const uint32_t smem_u = (uint32_t)__cvta_generic_to_shared(smh);

    const int tid  = threadIdx.x;
    const int lane = tid & 31;
    const int warp = tid >> 5;
    const int wq   = warp * 32;
    const int g    = lane >> 2;
    const int tg   = lane & 3;
    const int lrow  = lane & 15;
    const int lcol8 = (lane >> 4) * 8;

    const __half* Kbase = K + (size_t)b * SEQ * DM + h * DKH;
    const __half* Vtb   = Vt + (size_t)(b * HH + h) * DKH * SEQ;

    auto prefetch = [&](int t, int buf) {
#pragma unroll
        for (int i = 0; i < 8; i++) {
            int idx = tid + i * 128;        // 0..1023
            int arr = idx >> 9;             // 0 = K, 1 = Vt
            int r   = (idx >> 3) & 63;
            int u   = idx & 7;
            uint32_t off = r * 128 + ((u ^ (r & 7)) << 4);
            if (arr == 0)
                cp16(smem_u + buf * AT_TILE + off,
                     Kbase + (size_t)(t * 64 + r) * DM + u * 8);
            else
                cp16(smem_u + 2 * AT_TILE + buf * AT_TILE + off,
                     Vtb + (size_t)r * SEQ + t * 64 + u * 8);
        }
        cp_commit();
    };

    // hoist Q fragments (pre-scaled fp16) straight from gmem: 32 regs
    uint32_t qa[2][4][4];
    {
        const __half* Qb = Q + ((size_t)b * SEQ + q0 + wq) * DM + h * DKH;
#pragma unroll
        for (int mf = 0; mf < 2; mf++)
#pragma unroll
            for (int j = 0; j < 4; j++) {
                const __half* r0 = Qb + (size_t)(mf * 16 + g) * DM + j * 16 + 2 * tg;
                const __half* r1 = r0 + (size_t)8 * DM;
                qa[mf][j][0] = *(const uint32_t*)r0;
                qa[mf][j][1] = *(const uint32_t*)r1;
                qa[mf][j][2] = *(const uint32_t*)(r0 + 8);
                qa[mf][j][3] = *(const uint32_t*)(r1 + 8);
            }
    }

    prefetch(0, 0);

    float m_r[2][2], l_r[2][2];     // per-lane l partials
    float Oacc[2][8][4];
#pragma unroll
    for (int mf = 0; mf < 2; mf++) {
        m_r[mf][0] = -INFINITY; m_r[mf][1] = -INFINITY;
        l_r[mf][0] = 0.f;       l_r[mf][1] = 0.f;
#pragma unroll
        for (int nf = 0; nf < 8; nf++)
#pragma unroll
            for (int c = 0; c < 4; c++) Oacc[mf][nf][c] = 0.f;
    }

    int buf = 0;
    for (int t = 0; t < NKV; t++) {
        if (t + 1 < NKV) prefetch(t + 1, buf ^ 1);
        else             cp_commit();
        cp_wait<1>();
        __syncthreads();

        const uint32_t kt_u = smem_u + buf * AT_TILE;
        const uint32_t vt_u = smem_u + (2 + buf) * AT_TILE;

#pragma unroll
        for (int kc = 0; kc < 2; kc++) {    // two 32-kv chunks
            // ---- S = Q @ K^T (warp: 32q x 32kv) ----
            float sacc[2][4][4];
#pragma unroll
            for (int mf = 0; mf < 2; mf++)
#pragma unroll
                for (int nf = 0; nf < 4; nf++)
#pragma unroll
                    for (int c = 0; c < 4; c++) sacc[mf][nf][c] = 0.f;

#pragma unroll
            for (int j = 0; j < 4; j++) {   // d k16-steps
                const int c0 = j * 16 + lcol8;
                uint32_t bf[4][2];
#pragma unroll
                for (int np = 0; np < 2; np++) {
                    uint32_t tq[4];
                    ldsm_x4(tq, kt_u + 2 * hx(kc * 32 + np * 16 + lrow, c0));
                    bf[2 * np][0]     = tq[0];
                    bf[2 * np + 1][0] = tq[1];
                    bf[2 * np][1]     = tq[2];
                    bf[2 * np + 1][1] = tq[3];
                }
#pragma unroll
                for (int nf = 0; nf < 4; nf++) {
                    mma_f16(sacc[0][nf], qa[0][j], bf[nf]);
                    mma_f16(sacc[1][nf], qa[1][j], bf[nf]);
                }
            }

            // ---- online softmax per m-fragment (rows g, g+8) ----
#pragma unroll
            for (int mf = 0; mf < 2; mf++) {
                float mx0 = -INFINITY, mx1 = -INFINITY;
#pragma unroll
                for (int nf = 0; nf < 4; nf++) {
                    mx0 = fmaxf(mx0, fmaxf(sacc[mf][nf][0], sacc[mf][nf][1]));
                    mx1 = fmaxf(mx1, fmaxf(sacc[mf][nf][2], sacc[mf][nf][3]));
                }
                mx0 = fmaxf(mx0, __shfl_xor_sync(0xffffffffu, mx0, 1));
                mx0 = fmaxf(mx0, __shfl_xor_sync(0xffffffffu, mx0, 2));
                mx1 = fmaxf(mx1, __shfl_xor_sync(0xffffffffu, mx1, 1));
                mx1 = fmaxf(mx1, __shfl_xor_sync(0xffffffffu, mx1, 2));

                const float mn0 = fmaxf(m_r[mf][0], mx0);
                const float mn1 = fmaxf(m_r[mf][1], mx1);
                const float al0 = __expf(m_r[mf][0] - mn0);
                const float al1 = __expf(m_r[mf][1] - mn1);

                float s0 = 0.f, s1 = 0.f;
#pragma unroll
                for (int nf = 0; nf < 4; nf++) {
                    float p0 = __expf(sacc[mf][nf][0] - mn0);
                    float p1 = __expf(sacc[mf][nf][1] - mn0);
                    float p2 = __expf(sacc[mf][nf][2] - mn1);
                    float p3 = __expf(sacc[mf][nf][3] - mn1);
                    sacc[mf][nf][0] = p0; sacc[mf][nf][1] = p1;
                    sacc[mf][nf][2] = p2; sacc[mf][nf][3] = p3;
                    s0 += p0 + p1;
                    s1 += p2 + p3;
                }
                m_r[mf][0] = mn0; m_r[mf][1] = mn1;
                l_r[mf][0] = l_r[mf][0] * al0 + s0;
                l_r[mf][1] = l_r[mf][1] * al1 + s1;

#pragma unroll
                for (int nf = 0; nf < 8; nf++) {
                    Oacc[mf][nf][0] *= al0; Oacc[mf][nf][1] *= al0;
                    Oacc[mf][nf][2] *= al1; Oacc[mf][nf][3] *= al1;
                }
            }

            // ---- O += P @ V : A-frag = packed S C-frag, V via ldmatrix ----
#pragma unroll
            for (int j2 = 0; j2 < 2; j2++) {   // kv k16-steps within chunk
                uint32_t af[2][4];
#pragma unroll
                for (int mf = 0; mf < 2; mf++) {
                    af[mf][0] = packh2(sacc[mf][2 * j2][0],     sacc[mf][2 * j2][1]);
                    af[mf][1] = packh2(sacc[mf][2 * j2][2],     sacc[mf][2 * j2][3]);
                    af[mf][2] = packh2(sacc[mf][2 * j2 + 1][0], sacc[mf][2 * j2 + 1][1]);
                    af[mf][3] = packh2(sacc[mf][2 * j2 + 1][2], sacc[mf][2 * j2 + 1][3]);
                }
                const int k0 = kc * 32 + j2 * 16 + lcol8;
                uint32_t bf[8][2];
#pragma unroll
                for (int np = 0; np < 4; np++) {
                    uint32_t tv[4];
                    ldsm_x4(tv, vt_u + 2 * hx(np * 16 + lrow, k0));
                    bf[2 * np][0]     = tv[0];
                    bf[2 * np + 1][0] = tv[1];
                    bf[2 * np][1]     = tv[2];
                    bf[2 * np + 1][1] = tv[3];
                }
#pragma unroll
                for (int nf = 0; nf < 8; nf++) {
                    mma_f16(Oacc[0][nf], af[0], bf[nf]);
                    mma_f16(Oacc[1][nf], af[1], bf[nf]);
                }
            }
        }

        __syncthreads();
        buf ^= 1;
    }

    // ---- epilogue: reduce l across quad, write fp16 ctx (natural) ----
#pragma unroll
    for (int mf = 0; mf < 2; mf++) {
        float l0 = l_r[mf][0], l1 = l_r[mf][1];
        l0 += __shfl_xor_sync(0xffffffffu, l0, 1);
        l0 += __shfl_xor_sync(0xffffffffu, l0, 2);
        l1 += __shfl_xor_sync(0xffffffffu, l1, 1);
        l1 += __shfl_xor_sync(0xffffffffu, l1, 2);
        const float inv0 = 1.f / l0;
        const float inv1 = 1.f / l1;
        __half* out = ctx + ((size_t)b * SEQ + q0 + wq + mf * 16) * DM + h * DKH;
#pragma unroll
        for (int nf = 0; nf < 8; nf++) {
            *(uint32_t*)&out[(size_t)g * DM + nf * 8 + tg * 2] =
                packh2(Oacc[mf][nf][0] * inv0, Oacc[mf][nf][1] * inv0);
            *(uint32_t*)&out[(size_t)(g + 8) * DM + nf * 8 + tg * 2] =
                packh2(Oacc[mf][nf][2] * inv1, Oacc[mf][nf][3] * inv1);
        }
    }
}

// ---------------------------------------------------------------------------
// Launch
// ---------------------------------------------------------------------------
extern "C" void kernel_launch(void* const* d_in, const int* in_sizes, int n_in,
                              void* d_out, int out_size)
{
    (void)in_sizes; (void)n_in; (void)out_size;
    const float* q  = (const float*)d_in[0];
    const float* k  = (const float*)d_in[1];
    const float* v  = (const float*)d_in[2];
    const float* Wq = (const float*)d_in[3];
    const float* Wk = (const float*)d_in[4];
    const float* Wv = (const float*)d_in[5];
    const float* Wo = (const float*)d_in[6];
    float* out = (float*)d_out;

    __half *hq, *hk, *hv, *hWq, *hWk, *hWv, *hWo;
    __half *gQ, *gK, *gVt, *gC;
    cudaGetSymbolAddress((void**)&hq,  h_q);
    cudaGetSymbolAddress((void**)&hk,  h_k);
    cudaGetSymbolAddress((void**)&hv,  h_v);
    cudaGetSymbolAddress((void**)&hWq, h_Wq);
    cudaGetSymbolAddress((void**)&hWk, h_Wk);
    cudaGetSymbolAddress((void**)&hWv, h_Wv);
    cudaGetSymbolAddress((void**)&hWo, h_Wo);
    cudaGetSymbolAddress((void**)&gQ,  g_Qh);
    cudaGetSymbolAddress((void**)&gK,  g_Kh);
    cudaGetSymbolAddress((void**)&gVt, g_Vt);
    cudaGetSymbolAddress((void**)&gC,  g_ctxh);

    static bool attr_set = false;
    if (!attr_set) {
        cudaFuncSetAttribute(attn_f16_kernel,
                             cudaFuncAttributeMaxDynamicSharedMemorySize, ATTN_SMEM);
        cudaFuncSetAttribute(gemm_qkv_kernel,
                             cudaFuncAttributeMaxDynamicSharedMemorySize, H_SMEM);
        cudaFuncSetAttribute(gemm_o_kernel,
                             cudaFuncAttributeMaxDynamicSharedMemorySize, H_SMEM);
        attr_set = true;
    }

    // ---- fused f32 -> f16 pre-convert (one launch, 7 tensors) ----
    const int n8_x = MTOT * DM / 8;
    const int n8_w = DM * DM / 8;
    ConvArgs ca;
    ca.src[0] = (const float4*)q;  ca.dst[0] = (uint4*)hq;  ca.n8[0] = n8_x;
    ca.src[1] = (const float4*)k;  ca.dst[1] = (uint4*)hk;  ca.n8[1] = n8_x;
    ca.src[2] = (const float4*)v;  ca.dst[2] = (uint4*)hv;  ca.n8[2] = n8_x;
    ca.src[3] = (const float4*)Wq; ca.dst[3] = (uint4*)hWq; ca.n8[3] = n8_w;
    ca.src[4] = (const float4*)Wk; ca.dst[4] = (uint4*)hWk; ca.n8[4] = n8_w;
    ca.src[5] = (const float4*)Wv; ca.dst[5] = (uint4*)hWv; ca.n8[5] = n8_w;
    ca.src[6] = (const float4*)Wo; ca.dst[6] = (uint4*)hWo; ca.n8[6] = n8_w;
    dim3 cgrid((n8_x + 1023) / 1024, 7);
    conv_all_kernel<<<cgrid, 256>>>(ca);

    // ---- fused Q/K/V projections ----
    QKVArgs qa;
    qa.A[0] = hq; qa.B[0] = hWq; qa.C[0] = gQ;
    qa.A[1] = hk; qa.B[1] = hWk; qa.C[1] = gK;
    qa.A[2] = hv; qa.B[2] = hWv; qa.C[2] = gVt;
    dim3 qgrid(DM / 128, MTOT / 128, 3);
    gemm_qkv_kernel<<<qgrid, 256, H_SMEM>>>(qa);

    // ---- attention ----
    dim3 agrid(BATCH * HH, SEQ / QTILE);
    attn_f16_kernel<<<agrid, 128, ATTN_SMEM>>>(gQ, gK, gVt, gC);

    // ---- output projection ----
    dim3 ogrid(DM / 128, MTOT / 128);
    gemm_o_kernel<<<ogrid, 256, H_SMEM>>>(gC, hWo, out);
}